// round 3
// baseline (speedup 1.0000x reference)
#include <cuda_runtime.h>

#define BB 8
#define HH 512
#define WW 512
#define NN 32

// Scratch (no allocations allowed anywhere)
__device__ int   g_xmin[BB * HH];
__device__ int   g_xmax[BB * HH];
__device__ float g_unit[BB * HH];

// ---------------------------------------------------------------------------
// Kernel 1a: per-row min/max column index of positive pixels in seg[...,1]
// Warp-per-row: grid (B, H/16), 512 threads = 16 warps = 16 rows per block.
// float2 loads fetch both channels coalesced; we test channel 1 (.y).
// ---------------------------------------------------------------------------
__global__ void rowminmax_kernel(const float* __restrict__ seg) {
    int b    = blockIdx.x;
    int h    = blockIdx.y * 16 + (threadIdx.x >> 5);
    int lane = threadIdx.x & 31;

    const float2* row = (const float2*)(seg + (size_t)(b * HH + h) * WW * 2);
    int mn = WW, mx = -1;
    #pragma unroll
    for (int i = 0; i < WW / 32; ++i) {
        int c = lane + i * 32;
        float2 v = row[c];
        if (v.y > 0.0f) { mn = min(mn, c); mx = max(mx, c); }
    }
    #pragma unroll
    for (int o = 16; o; o >>= 1) {
        mn = min(mn, __shfl_down_sync(0xffffffffu, mn, o));
        mx = max(mx, __shfl_down_sync(0xffffffffu, mx, o));
    }
    if (lane == 0) {
        g_xmin[b * HH + h] = mn;
        g_xmax[b * HH + h] = mx;
    }
}

// ---------------------------------------------------------------------------
// Kernel 1b: per-image weighted least squares fit -> unit[b][h]
// 8 blocks, 512 threads (thread == row h). f64 sums (tighter than f32 ref).
// ---------------------------------------------------------------------------
__global__ void fit_kernel() {
    int b    = blockIdx.x;
    int t    = threadIdx.x;          // row index h
    int lane = t & 31;
    int wi   = t >> 5;

    __shared__ unsigned s_vw[16];
    __shared__ double   s_red[16];
    __shared__ double   s_sums[7];

    int mn = g_xmin[b * HH + t];
    int mx = g_xmax[b * HH + t];
    bool present = (mx >= 0);
    bool valid   = present && (mn != mx);

    unsigned ball = __ballot_sync(0xffffffffu, valid);
    if (lane == 0) s_vw[wi] = ball;
    __syncthreads();

    int nv = 0, rank = 0;
    #pragma unroll
    for (int j = 0; j < 16; ++j) {
        int pc = __popc(s_vw[j]);
        nv += pc;
        if (j < wi) rank += pc;
    }
    rank += __popc(s_vw[wi] & ((1u << lane) - 1u));

    int drop = (int)((float)nv * 0.15f);   // f32 mult then trunc, mirrors jnp
    if (drop < 1) drop = 1;
    bool keep = valid && (rank >= drop) && (rank < nv - drop);

    double w  = keep ? 1.0 : 0.0;
    double y  = (double)t;
    double xl = (double)mn;
    double xr = (double)mx;

    double vals[7];
    vals[0] = w;
    vals[1] = w * y;
    vals[2] = w * y * y;
    vals[3] = w * xl;
    vals[4] = w * y * xl;
    vals[5] = w * xr;
    vals[6] = w * y * xr;

    for (int q = 0; q < 7; ++q) {
        double v = vals[q];
        #pragma unroll
        for (int o = 16; o; o >>= 1) v += __shfl_down_sync(0xffffffffu, v, o);
        if (lane == 0) s_red[wi] = v;
        __syncthreads();
        if (t == 0) {
            double acc = 0.0;
            #pragma unroll
            for (int j = 0; j < 16; ++j) acc += s_red[j];
            s_sums[q] = acc;
        }
        __syncthreads();
    }

    double Sw  = s_sums[0], Sy = s_sums[1], Syy = s_sums[2];
    double Sxl = s_sums[3], Syxl = s_sums[4];
    double Sxr = s_sums[5], Syxr = s_sums[6];

    double det = Syy * Sw - Sy * Sy;
    double sl_l = 0.0, ic_l = 0.0, sl_r = 0.0, ic_r = 0.0;
    if (det > 0.0) {
        double inv = 1.0 / det;
        sl_l = ( Sw * Syxl - Sy  * Sxl) * inv;
        ic_l = (-Sy * Syxl + Syy * Sxl) * inv;
        sl_r = ( Sw * Syxr - Sy  * Sxr) * inv;
        ic_r = (-Sy * Syxr + Syy * Sxr) * inv;
    }
    float yf = (float)t;
    float pl = yf * (float)sl_l + (float)ic_l;
    float pr = yf * (float)sl_r + (float)ic_r;
    float width = fmaxf(pr - pl, 1.0f);
    g_unit[b * HH + t] = 3.25f / width;
}

// ---------------------------------------------------------------------------
// Block reduction helpers (512 threads = 16 warps). Result valid on thread 0.
// ---------------------------------------------------------------------------
__device__ __forceinline__ float blockReduceSum(float v, float* s) {
    int lane = threadIdx.x & 31, wi = threadIdx.x >> 5;
    #pragma unroll
    for (int o = 16; o; o >>= 1) v += __shfl_down_sync(0xffffffffu, v, o);
    if (lane == 0) s[wi] = v;
    __syncthreads();
    float r = (threadIdx.x < 16) ? s[threadIdx.x] : 0.0f;
    if (wi == 0) {
        #pragma unroll
        for (int o = 8; o; o >>= 1) r += __shfl_down_sync(0xffffffffu, r, o);
    }
    __syncthreads();
    return r;
}

__device__ __forceinline__ float blockReduceMax(float v, float* s) {
    int lane = threadIdx.x & 31, wi = threadIdx.x >> 5;
    #pragma unroll
    for (int o = 16; o; o >>= 1) v = fmaxf(v, __shfl_down_sync(0xffffffffu, v, o));
    if (lane == 0) s[wi] = v;
    __syncthreads();
    float r = (threadIdx.x < 16) ? s[threadIdx.x] : -3.402823466e+38f;
    if (wi == 0) {
        #pragma unroll
        for (int o = 8; o; o >>= 1) r = fmaxf(r, __shfl_down_sync(0xffffffffu, r, o));
    }
    __syncthreads();
    return r;
}

// ---------------------------------------------------------------------------
// Kernel 2: main streaming reduction over pad [B,N,H,W].
// 256 blocks (one per (b,n) tile, 1 MB each), 512 threads.
// Thread layout: phase = t>>7 (row residue mod 4), cg = t&127 (4 cols, float4).
// Steady-state loop has NO cross-lane ops: per-thread occupancy bitmask,
// combined via one __reduce_or_sync per 32 iterations -> deep load batching.
// ---------------------------------------------------------------------------
__global__ void __launch_bounds__(512, 2) reduce_kernel(
    const float* __restrict__ pad, float* __restrict__ out) {
    int bn = blockIdx.x;            // b*32 + n
    int b  = bn >> 5;
    const float* base = pad + (size_t)bn * HH * WW;

    int t     = threadIdx.x;
    int lane  = t & 31;
    int wi    = t >> 5;
    int phase = t >> 7;             // 0..3
    int cg    = t & 127;            // column group (4 floats)

    __shared__ float    s_u[HH];
    __shared__ float    s_u2[HH];
    __shared__ float    s_colp[4][WW];   // per-phase column sums
    __shared__ unsigned s_occ[16][4];    // per-warp row-occupancy bitmasks
    __shared__ float    s_red[16];

    float u = g_unit[b * HH + t];
    s_u[t]  = u;
    s_u2[t] = u * u;
    __syncthreads();

    float inst = 0.0f;
    float col0 = 0.0f, col1 = 0.0f, col2 = 0.0f, col3 = 0.0f;

    // 4 chunks of 32 iterations; one cross-lane OR per chunk.
    #pragma unroll
    for (int ch = 0; ch < 4; ++ch) {
        unsigned thmask = 0;
        #pragma unroll 8
        for (int j = 0; j < 32; ++j) {
            int i = ch * 32 + j;
            int h = 4 * i + phase;
            float4 v = *(const float4*)(base + (size_t)h * WW + 4 * cg);
            float uu = s_u[h];
            float u2 = s_u2[h];
            inst += u2 * ((v.x + v.y) + (v.z + v.w));
            col0 += uu * v.x;
            col1 += uu * v.y;
            col2 += uu * v.z;
            col3 += uu * v.w;
            float pm = fmaxf(fmaxf(v.x, v.y), fmaxf(v.z, v.w));
            thmask |= (pm > 0.5f ? 1u : 0u) << j;
        }
        unsigned m = __reduce_or_sync(0xffffffffu, thmask);
        if (lane == 0) s_occ[wi][ch] = m;
    }

    // per-phase column sums to shared (disjoint writes, deterministic)
    *(float4*)&s_colp[phase][4 * cg] = make_float4(col0, col1, col2, col3);
    __syncthreads();

    // vertical: thread t == row h; OR occupancy across the 4 warps of h's phase
    int ph = t & 3;
    int ii = t >> 2;
    int wd = ii >> 5;
    unsigned oc = (s_occ[4 * ph + 0][wd] | s_occ[4 * ph + 1][wd] |
                   s_occ[4 * ph + 2][wd] | s_occ[4 * ph + 3][wd]) >> (ii & 31);
    float vert = (oc & 1u) ? s_u[t] : 0.0f;

    // horizontal: thread t == column w; combine the 4 phase partial sums
    float colsum = s_colp[0][t] + s_colp[1][t] + s_colp[2][t] + s_colp[3][t];

    float inst_sum = blockReduceSum(inst, s_red);
    float vert_sum = blockReduceSum(vert, s_red);
    float horiz    = blockReduceMax(colsum, s_red);

    if (t == 0) {
        out[bn * 3 + 0] = inst_sum;
        out[bn * 3 + 1] = horiz;
        out[bn * 3 + 2] = vert_sum;
    }
}

// ---------------------------------------------------------------------------
extern "C" void kernel_launch(void* const* d_in, const int* in_sizes, int n_in,
                              void* d_out, int out_size) {
    const float* seg;
    const float* pad;
    if (in_sizes[0] == BB * HH * WW * 2) {
        seg = (const float*)d_in[0];
        pad = (const float*)d_in[1];
    } else {
        seg = (const float*)d_in[1];
        pad = (const float*)d_in[0];
    }
    float* out = (float*)d_out;

    rowminmax_kernel<<<dim3(BB, HH / 16), 512>>>(seg);
    fit_kernel<<<BB, 512>>>();
    reduce_kernel<<<BB * NN, 512>>>(pad, out);
}

// round 8
// speedup vs baseline: 1.0823x; 1.0823x over previous
#include <cuda_runtime.h>

#define BB 8
#define HH 512
#define WW 512
#define NN 32

// Scratch (no allocations allowed anywhere)
__device__ int   g_xmin[BB * HH];
__device__ int   g_xmax[BB * HH];
__device__ float g_unit[BB * HH];

// ---------------------------------------------------------------------------
// Kernel 1a: per-row min/max column index of positive pixels in seg[...,1]
// Warp-per-row: grid (B, H/16), 512 threads = 16 warps = 16 rows per block.
// float4 loads: lane covers 2 columns (ch1 = .y and .w); 8 unrolled LDG.128
// -> 32 payload regs, deep MLP batching.
// ---------------------------------------------------------------------------
__global__ void rowminmax_kernel(const float* __restrict__ seg) {
    int b    = blockIdx.x;
    int h    = blockIdx.y * 16 + (threadIdx.x >> 5);
    int lane = threadIdx.x & 31;

    const float4* row4 = (const float4*)(seg + (size_t)(b * HH + h) * WW * 2);
    int mn = WW, mx = -1;
    #pragma unroll
    for (int i = 0; i < (WW * 2 / 4) / 32; ++i) {   // 8 iterations
        int idx = lane + i * 32;
        float4 v = __ldcs(&row4[idx]);
        int c = idx * 2;
        if (v.y > 0.0f) { mn = min(mn, c);     mx = max(mx, c);     }
        if (v.w > 0.0f) { mn = min(mn, c + 1); mx = max(mx, c + 1); }
    }
    #pragma unroll
    for (int o = 16; o; o >>= 1) {
        mn = min(mn, __shfl_down_sync(0xffffffffu, mn, o));
        mx = max(mx, __shfl_down_sync(0xffffffffu, mx, o));
    }
    if (lane == 0) {
        g_xmin[b * HH + h] = mn;
        g_xmax[b * HH + h] = mx;
    }
}

// ---------------------------------------------------------------------------
// Kernel 1b: per-image weighted least squares fit -> unit[b][h]
// 8 blocks, 512 threads (thread == row h). f64 sums (tighter than f32 ref).
// Cross-warp combine parallelized: one warp per quantity (7 warps), one sync.
// ---------------------------------------------------------------------------
__global__ void fit_kernel() {
    int b    = blockIdx.x;
    int t    = threadIdx.x;          // row index h
    int lane = t & 31;
    int wi   = t >> 5;

    __shared__ unsigned s_vw[16];
    __shared__ double   s_red[7][16];
    __shared__ double   s_sums[7];

    int mn = g_xmin[b * HH + t];
    int mx = g_xmax[b * HH + t];
    bool present = (mx >= 0);
    bool valid   = present && (mn != mx);

    unsigned ball = __ballot_sync(0xffffffffu, valid);
    if (lane == 0) s_vw[wi] = ball;
    __syncthreads();

    int nv = 0, rank = 0;
    #pragma unroll
    for (int j = 0; j < 16; ++j) {
        int pc = __popc(s_vw[j]);
        nv += pc;
        if (j < wi) rank += pc;
    }
    rank += __popc(s_vw[wi] & ((1u << lane) - 1u));

    int drop = (int)((float)nv * 0.15f);   // f32 mult then trunc, mirrors jnp
    if (drop < 1) drop = 1;
    bool keep = valid && (rank >= drop) && (rank < nv - drop);

    double w  = keep ? 1.0 : 0.0;
    double y  = (double)t;
    double xl = (double)mn;
    double xr = (double)mx;

    double vals[7];
    vals[0] = w;
    vals[1] = w * y;
    vals[2] = w * y * y;
    vals[3] = w * xl;
    vals[4] = w * y * xl;
    vals[5] = w * xr;
    vals[6] = w * y * xr;

    #pragma unroll
    for (int q = 0; q < 7; ++q) {
        double v = vals[q];
        #pragma unroll
        for (int o = 16; o; o >>= 1) v += __shfl_down_sync(0xffffffffu, v, o);
        if (lane == 0) s_red[q][wi] = v;
    }
    __syncthreads();

    // warp q (q<7) reduces quantity q's 16 per-warp partials
    if (wi < 7) {
        double v = (lane < 16) ? s_red[wi][lane] : 0.0;
        #pragma unroll
        for (int o = 8; o; o >>= 1) v += __shfl_down_sync(0xffffffffu, v, o);
        if (lane == 0) s_sums[wi] = v;
    }
    __syncthreads();

    double Sw  = s_sums[0], Sy = s_sums[1], Syy = s_sums[2];
    double Sxl = s_sums[3], Syxl = s_sums[4];
    double Sxr = s_sums[5], Syxr = s_sums[6];

    double det = Syy * Sw - Sy * Sy;
    double sl_l = 0.0, ic_l = 0.0, sl_r = 0.0, ic_r = 0.0;
    if (det > 0.0) {
        double inv = 1.0 / det;
        sl_l = ( Sw * Syxl - Sy  * Sxl) * inv;
        ic_l = (-Sy * Syxl + Syy * Sxl) * inv;
        sl_r = ( Sw * Syxr - Sy  * Sxr) * inv;
        ic_r = (-Sy * Syxr + Syy * Sxr) * inv;
    }
    float yf = (float)t;
    float pl = yf * (float)sl_l + (float)ic_l;
    float pr = yf * (float)sl_r + (float)ic_r;
    float width = fmaxf(pr - pl, 1.0f);
    g_unit[b * HH + t] = 3.25f / width;
}

// ---------------------------------------------------------------------------
// Block reduction helpers (512 threads = 16 warps). Result valid on thread 0.
// ---------------------------------------------------------------------------
__device__ __forceinline__ float blockReduceSum(float v, float* s) {
    int lane = threadIdx.x & 31, wi = threadIdx.x >> 5;
    #pragma unroll
    for (int o = 16; o; o >>= 1) v += __shfl_down_sync(0xffffffffu, v, o);
    if (lane == 0) s[wi] = v;
    __syncthreads();
    float r = (threadIdx.x < 16) ? s[threadIdx.x] : 0.0f;
    if (wi == 0) {
        #pragma unroll
        for (int o = 8; o; o >>= 1) r += __shfl_down_sync(0xffffffffu, r, o);
    }
    __syncthreads();
    return r;
}

__device__ __forceinline__ float blockReduceMax(float v, float* s) {
    int lane = threadIdx.x & 31, wi = threadIdx.x >> 5;
    #pragma unroll
    for (int o = 16; o; o >>= 1) v = fmaxf(v, __shfl_down_sync(0xffffffffu, v, o));
    if (lane == 0) s[wi] = v;
    __syncthreads();
    float r = (threadIdx.x < 16) ? s[threadIdx.x] : -3.402823466e+38f;
    if (wi == 0) {
        #pragma unroll
        for (int o = 8; o; o >>= 1) r = fmaxf(r, __shfl_down_sync(0xffffffffu, r, o));
    }
    __syncthreads();
    return r;
}

// ---------------------------------------------------------------------------
// Kernel 2: main streaming reduction over pad [B,N,H,W].
// 256 blocks (one per (b,n) tile, 1 MB each), 512 threads.
// Thread layout: phase = t>>7 (row residue mod 4), cg = t&127 (4 cols, float4).
// Steady-state loop: __ldcs streaming loads, no cross-lane ops, one LDS/iter.
// ---------------------------------------------------------------------------
__global__ void __launch_bounds__(512, 2) reduce_kernel(
    const float* __restrict__ pad, float* __restrict__ out) {
    int bn = blockIdx.x;            // b*32 + n
    int b  = bn >> 5;
    const float* base = pad + (size_t)bn * HH * WW;

    int t     = threadIdx.x;
    int lane  = t & 31;
    int wi    = t >> 5;
    int phase = t >> 7;             // 0..3
    int cg    = t & 127;            // column group (4 floats)

    __shared__ float    s_u[HH];
    __shared__ float    s_colp[4][WW];   // per-phase column sums
    __shared__ unsigned s_occ[16][4];    // per-warp row-occupancy bitmasks
    __shared__ float    s_red[16];

    float u = g_unit[b * HH + t];
    s_u[t] = u;
    __syncthreads();

    float inst = 0.0f;
    float col0 = 0.0f, col1 = 0.0f, col2 = 0.0f, col3 = 0.0f;

    // 4 chunks of 32 iterations; one cross-lane OR per chunk.
    #pragma unroll
    for (int ch = 0; ch < 4; ++ch) {
        unsigned thmask = 0;
        #pragma unroll 8
        for (int j = 0; j < 32; ++j) {
            int i = ch * 32 + j;
            int h = 4 * i + phase;
            float4 v = __ldcs((const float4*)(base + (size_t)h * WW + 4 * cg));
            float uu = s_u[h];
            inst += (uu * uu) * ((v.x + v.y) + (v.z + v.w));
            col0 += uu * v.x;
            col1 += uu * v.y;
            col2 += uu * v.z;
            col3 += uu * v.w;
            float pm = fmaxf(fmaxf(v.x, v.y), fmaxf(v.z, v.w));
            thmask |= (pm > 0.5f ? 1u : 0u) << j;
        }
        unsigned m = __reduce_or_sync(0xffffffffu, thmask);
        if (lane == 0) s_occ[wi][ch] = m;
    }

    // per-phase column sums to shared (disjoint writes, deterministic)
    *(float4*)&s_colp[phase][4 * cg] = make_float4(col0, col1, col2, col3);
    __syncthreads();

    // vertical: thread t == row h; OR occupancy across the 4 warps of h's phase
    int ph = t & 3;
    int ii = t >> 2;
    int wd = ii >> 5;
    unsigned oc = (s_occ[4 * ph + 0][wd] | s_occ[4 * ph + 1][wd] |
                   s_occ[4 * ph + 2][wd] | s_occ[4 * ph + 3][wd]) >> (ii & 31);
    float vert = (oc & 1u) ? s_u[t] : 0.0f;

    // horizontal: thread t == column w; combine the 4 phase partial sums
    float colsum = s_colp[0][t] + s_colp[1][t] + s_colp[2][t] + s_colp[3][t];

    float inst_sum = blockReduceSum(inst, s_red);
    float vert_sum = blockReduceSum(vert, s_red);
    float horiz    = blockReduceMax(colsum, s_red);

    if (t == 0) {
        out[bn * 3 + 0] = inst_sum;
        out[bn * 3 + 1] = horiz;
        out[bn * 3 + 2] = vert_sum;
    }
}

// ---------------------------------------------------------------------------
extern "C" void kernel_launch(void* const* d_in, const int* in_sizes, int n_in,
                              void* d_out, int out_size) {
    const float* seg;
    const float* pad;
    if (in_sizes[0] == BB * HH * WW * 2) {
        seg = (const float*)d_in[0];
        pad = (const float*)d_in[1];
    } else {
        seg = (const float*)d_in[1];
        pad = (const float*)d_in[0];
    }
    float* out = (float*)d_out;

    rowminmax_kernel<<<dim3(BB, HH / 16), 512>>>(seg);
    fit_kernel<<<BB, 512>>>();
    reduce_kernel<<<BB * NN, 512>>>(pad, out);
}